// round 1
// baseline (speedup 1.0000x reference)
#include <cuda_runtime.h>

#define NB 32       // batch
#define NS 8192     // seq len
#define ND 32       // hidden dim
#define NG 128      // 4*ND gates
#define NC 256      // output cats

// hs buffer: (B, S, D) float32 = 33.5 MB static device scratch (no cudaMalloc allowed)
__device__ float g_hs[NB * NS * ND];

__device__ __forceinline__ float fast_sigmoid(float x) {
    // 1/(1+e^-x) via MUFU.EX2 + MUFU.RCP chain, rel err ~2^-21
    return __fdividef(1.0f, 1.0f + __expf(-x));
}

__device__ __forceinline__ float fast_tanh(float x) {
    // tanh(x) = sign(x) * (1 - e^{-2|x|}) / (1 + e^{-2|x|}); overflow-safe
    float ax = fabsf(x);
    float t  = __expf(-2.0f * ax);
    float r  = __fdividef(1.0f - t, 1.0f + t);
    return copysignf(r, x);
}

// One block per batch row. 128 threads = 4 warps (gate i,f,g,o), lane = hidden dim.
// h and c replicated per-lane across all 4 warps -> single __syncthreads per step.
__global__ void __launch_bounds__(128, 1) scan_kernel(
    const float* __restrict__ x,      // (B, S)
    const float* __restrict__ bos,    // (D)
    const float* __restrict__ W_in,   // (1, D)
    const float* __restrict__ b_in,   // (D)
    const float* __restrict__ Wx,     // (D, 4D)
    const float* __restrict__ Wh,     // (D, 4D)
    const float* __restrict__ b_lstm) // (4D)
{
    const int b   = blockIdx.x;
    const int tid = threadIdx.x;
    const int w   = tid >> 5;   // gate index: 0=i 1=f 2=g 3=o
    const int l   = tid & 31;   // hidden dim
    const int k   = tid;        // gate column 0..127

    __shared__ float gbuf[2][4][32];   // ping-pong activated-gate exchange

    // Wh column for this thread, resident in registers
    float wh[ND];
#pragma unroll
    for (int d = 0; d < ND; d++) wh[d] = Wh[d * NG + k];

    // Rank-1 input path: z_in = x_prev*u + v ; step 0 uses bos embedding
    float u = 0.f, v = 0.f, z0 = 0.f;
#pragma unroll
    for (int d = 0; d < ND; d++) {
        float wx = Wx[d * NG + k];
        u  = fmaf(W_in[d], wx, u);
        v  = fmaf(b_in[d], wx, v);
        z0 = fmaf(bos[d],  wx, z0);
    }
    float bl = b_lstm[k];
    v  += bl;
    z0 += bl;

    float c = 0.f, h = 0.f;     // state for dim l (replicated across warps)
    float zbase = z0;
    const float* xb = x + (size_t)b * NS;
    int p = 0;

    for (int s = 0; s < NS; s++) {
        // prefetch x feeding step s+1 (off critical path)
        float xn = __ldg(&xb[s]);

        // z_k = zbase + sum_d h[d] * Wh[d,k]  (h broadcast via warp shuffle)
        float a0 = zbase, a1 = 0.f, a2 = 0.f, a3 = 0.f;
#pragma unroll
        for (int d = 0; d < ND; d += 4) {
            a0 = fmaf(__shfl_sync(0xffffffffu, h, d + 0), wh[d + 0], a0);
            a1 = fmaf(__shfl_sync(0xffffffffu, h, d + 1), wh[d + 1], a1);
            a2 = fmaf(__shfl_sync(0xffffffffu, h, d + 2), wh[d + 2], a2);
            a3 = fmaf(__shfl_sync(0xffffffffu, h, d + 3), wh[d + 3], a3);
        }
        float z = (a0 + a1) + (a2 + a3);

        // per-gate activation (warp-uniform branch)
        float act = (w == 2) ? fast_tanh(z) : fast_sigmoid(z);
        gbuf[p][w][l] = act;

        // next step's input contribution, hidden under barrier wait
        zbase = fmaf(xn, u, v);

        __syncthreads();

        float i_ = gbuf[p][0][l];
        float f_ = gbuf[p][1][l];
        float g_ = gbuf[p][2][l];
        float o_ = gbuf[p][3][l];

        c = fmaf(f_, c, i_ * g_);
        h = o_ * fast_tanh(c);

        if (w == 0) g_hs[((size_t)b * NS + s) * ND + l] = h;
        p ^= 1;
    }
}

// Epilogue: logits(B,S,C) = hs(B,S,D) @ W_out(D,C) + b_out.
// 8192 blocks x 256 threads; each block handles 32 (b,s) rows, thread = one col.
// W_out column held in registers; h tile staged in smem, read as float4.
__global__ void __launch_bounds__(256, 2) out_kernel(
    const float* __restrict__ W_out,  // (D, C)
    const float* __restrict__ b_out,  // (C)
    float* __restrict__ out)          // (B, S, C)
{
    __shared__ float hsm[32 * ND];
    const int c = threadIdx.x;
    const size_t row0 = (size_t)blockIdx.x * 32;

    float wc[ND];
#pragma unroll
    for (int d = 0; d < ND; d++) wc[d] = W_out[d * NC + c];
    const float bias = b_out[c];

    // stage 32 rows x 32 floats of hs (coalesced, one float4 per thread)
    const float4* src = (const float4*)(g_hs + row0 * ND);
    ((float4*)hsm)[c] = src[c];
    __syncthreads();

#pragma unroll 4
    for (int r = 0; r < 32; r++) {
        const float4* hr = (const float4*)(hsm + r * ND);
        float hv[ND];
#pragma unroll
        for (int j = 0; j < 8; j++) {
            float4 t = hr[j];
            hv[4 * j + 0] = t.x;
            hv[4 * j + 1] = t.y;
            hv[4 * j + 2] = t.z;
            hv[4 * j + 3] = t.w;
        }
        float a0 = bias, a1 = 0.f, a2 = 0.f, a3 = 0.f;
#pragma unroll
        for (int d = 0; d < ND; d += 4) {
            a0 = fmaf(hv[d + 0], wc[d + 0], a0);
            a1 = fmaf(hv[d + 1], wc[d + 1], a1);
            a2 = fmaf(hv[d + 2], wc[d + 2], a2);
            a3 = fmaf(hv[d + 3], wc[d + 3], a3);
        }
        out[(row0 + r) * NC + c] = (a0 + a1) + (a2 + a3);
    }
}

extern "C" void kernel_launch(void* const* d_in, const int* in_sizes, int n_in,
                              void* d_out, int out_size)
{
    const float* x      = (const float*)d_in[0];
    const float* bos    = (const float*)d_in[1];
    const float* W_in   = (const float*)d_in[2];
    const float* b_in   = (const float*)d_in[3];
    const float* Wx     = (const float*)d_in[4];
    const float* Wh     = (const float*)d_in[5];
    const float* b_lstm = (const float*)d_in[6];
    const float* W_out  = (const float*)d_in[7];
    const float* b_out  = (const float*)d_in[8];

    scan_kernel<<<NB, 128>>>(x, bos, W_in, b_in, Wx, Wh, b_lstm);
    out_kernel<<<(NB * NS) / 32, 256>>>(W_out, b_out, (float*)d_out);
}

// round 2
// speedup vs baseline: 2.6837x; 2.6837x over previous
#include <cuda_runtime.h>

#define NB 32       // batch
#define NS 8192     // seq len
#define ND 32       // hidden dim
#define NG 128      // 4*ND gates
#define NC 256      // output cats

// hs buffer: (B, S, D) float32 = 33.5 MB static device scratch
__device__ float g_hs[NB * NS * ND];

__device__ __forceinline__ float tanh_fast(float x) {
    float y;
    asm("tanh.approx.f32 %0, %1;" : "=f"(y) : "f"(x));
    return y;
}
__device__ __forceinline__ float sigmoid_fast(float x) {
    // sigma(x) = 0.5*tanh(x/2) + 0.5  (one MUFU.TANH + mul + fma)
    return fmaf(0.5f, tanh_fast(0.5f * x), 0.5f);
}

// One block per batch row. 128 threads = 4 warps (gate i,f,g,o), lane = hidden dim.
// h replicated per-warp in private smem buffers -> allgather via 8 broadcast LDS.128.
// Gate exchange via transposed smem tile -> single LDS.128 after the one barrier/step.
__global__ void __launch_bounds__(128, 1) scan_kernel(
    const float* __restrict__ x,      // (B, S)
    const float* __restrict__ bos,    // (D)
    const float* __restrict__ W_in,   // (1, D)
    const float* __restrict__ b_in,   // (D)
    const float* __restrict__ Wx,     // (D, 4D)
    const float* __restrict__ Wh,     // (D, 4D)
    const float* __restrict__ b_lstm) // (4D)
{
    const int b   = blockIdx.x;
    const int tid = threadIdx.x;
    const int w   = tid >> 5;   // gate index: 0=i 1=f 2=g 3=o
    const int l   = tid & 31;   // hidden dim
    const int k   = tid;        // gate column 0..127

    __shared__ float4 gbuf[2][32];      // [parity][dim] = {i,f,g,o} activated
    __shared__ float  hbuf[2][4][32];   // [parity][warp][dim] per-warp private h

    // Wh column for this thread, resident in registers
    float wh[ND];
#pragma unroll
    for (int d = 0; d < ND; d++) wh[d] = Wh[d * NG + k];

    // Rank-1 input path: z_in = x_prev*u + v ; step 0 uses bos embedding
    float u = 0.f, v = 0.f, z0 = 0.f;
#pragma unroll
    for (int d = 0; d < ND; d++) {
        float wx = Wx[d * NG + k];
        u  = fmaf(W_in[d], wx, u);
        v  = fmaf(b_in[d], wx, v);
        z0 = fmaf(bos[d],  wx, z0);
    }
    float bl = b_lstm[k];
    v  += bl;
    z0 += bl;

    float c = 0.f;
    hbuf[1][w][l] = 0.f;        // parity-0 iteration reads hbuf[1]
    float zbase = z0;
    const float* xb = x + (size_t)b * NS;
    float* hs_out = g_hs + (size_t)b * NS * ND + l;

#define STEP(P, S_) do {                                                    \
        float xn = __ldg(xb + (S_));                                        \
        __syncwarp();                                                       \
        const float4* hp = (const float4*)hbuf[(P) ^ 1][w];                 \
        float a0 = zbase, a1 = 0.f, a2 = 0.f, a3 = 0.f;                     \
        _Pragma("unroll")                                                   \
        for (int j = 0; j < 8; j++) {                                       \
            float4 q = hp[j];                                               \
            a0 = fmaf(q.x, wh[4 * j + 0], a0);                              \
            a1 = fmaf(q.y, wh[4 * j + 1], a1);                              \
            a2 = fmaf(q.z, wh[4 * j + 2], a2);                              \
            a3 = fmaf(q.w, wh[4 * j + 3], a3);                              \
        }                                                                   \
        float z = (a0 + a1) + (a2 + a3);                                    \
        float act = (w == 2) ? tanh_fast(z) : sigmoid_fast(z);              \
        ((float*)&gbuf[(P)][l])[w] = act;                                   \
        zbase = fmaf(xn, u, v);                                             \
        __syncthreads();                                                    \
        float4 g4 = gbuf[(P)][l];                                           \
        c = fmaf(g4.y, c, g4.x * g4.z);                                     \
        float h = g4.w * tanh_fast(c);                                      \
        hbuf[(P)][w][l] = h;                                                \
        if (w == 0) hs_out[(size_t)(S_) * ND] = h;                          \
    } while (0)

    for (int s = 0; s < NS; s += 2) {
        STEP(0, s);
        STEP(1, s + 1);
    }
#undef STEP
}

// Epilogue: logits(B,S,C) = hs(B,S,D) @ W_out(D,C) + b_out.
// 8192 blocks x 256 threads; block handles 32 (b,s) rows, thread = one output col.
__global__ void __launch_bounds__(256, 4) out_kernel(
    const float* __restrict__ W_out,  // (D, C)
    const float* __restrict__ b_out,  // (C)
    float* __restrict__ out)          // (B, S, C)
{
    __shared__ float hsm[32 * ND];
    const int cc = threadIdx.x;
    const size_t row0 = (size_t)blockIdx.x * 32;

    float wc[ND];
#pragma unroll
    for (int d = 0; d < ND; d++) wc[d] = W_out[d * NC + cc];
    const float bias = b_out[cc];

    // stage 32 rows x 32 floats of hs (coalesced, one float4 per thread)
    ((float4*)hsm)[cc] = ((const float4*)(g_hs + row0 * ND))[cc];
    __syncthreads();

#pragma unroll 4
    for (int r = 0; r < 32; r++) {
        const float4* hr = (const float4*)(hsm + r * ND);
        float a0 = bias, a1 = 0.f, a2 = 0.f, a3 = 0.f;
#pragma unroll
        for (int j = 0; j < 8; j++) {
            float4 t = hr[j];
            a0 = fmaf(t.x, wc[4 * j + 0], a0);
            a1 = fmaf(t.y, wc[4 * j + 1], a1);
            a2 = fmaf(t.z, wc[4 * j + 2], a2);
            a3 = fmaf(t.w, wc[4 * j + 3], a3);
        }
        out[(row0 + r) * NC + cc] = (a0 + a1) + (a2 + a3);
    }
}

extern "C" void kernel_launch(void* const* d_in, const int* in_sizes, int n_in,
                              void* d_out, int out_size)
{
    const float* x      = (const float*)d_in[0];
    const float* bos    = (const float*)d_in[1];
    const float* W_in   = (const float*)d_in[2];
    const float* b_in   = (const float*)d_in[3];
    const float* Wx     = (const float*)d_in[4];
    const float* Wh     = (const float*)d_in[5];
    const float* b_lstm = (const float*)d_in[6];
    const float* W_out  = (const float*)d_in[7];
    const float* b_out  = (const float*)d_in[8];

    scan_kernel<<<NB, 128>>>(x, bos, W_in, b_in, Wx, Wh, b_lstm);
    out_kernel<<<(NB * NS) / 32, 256>>>(W_out, b_out, (float*)d_out);
}

// round 3
// speedup vs baseline: 2.7118x; 1.0105x over previous
#include <cuda_runtime.h>
#include <cstdint>

#define NB 32       // batch
#define NS 8192     // seq len
#define ND 32       // hidden dim
#define NG 128      // 4*ND gates
#define NC 256      // output cats
#define CHUNK 32    // steps per producer->consumer handoff
#define NCHUNK (NS / CHUNK)
#define RING 64     // 2 chunks of h history in smem

// named barrier ids (0 reserved for __syncthreads)
#define B_READY 1   // producers arrive, consumers sync   (chunk published)
#define B_FREE  2   // consumers arrive, producers sync   (chunk consumed)
#define B_SCAN  3   // scan-internal per-step barrier (128 threads)

__device__ __forceinline__ float tanh_fast(float x) {
    float y;
    asm("tanh.approx.f32 %0, %1;" : "=f"(y) : "f"(x));
    return y;
}
__device__ __forceinline__ uint64_t pack2(float lo, float hi) {
    uint64_t r;
    asm("mov.b64 %0, {%1, %2};" : "=l"(r) : "f"(lo), "f"(hi));
    return r;
}
__device__ __forceinline__ void unpack2(float& lo, float& hi, uint64_t v) {
    asm("mov.b64 {%0, %1}, %2;" : "=f"(lo), "=f"(hi) : "l"(v));
}
__device__ __forceinline__ void fma2(uint64_t& acc, uint64_t a, uint64_t b) {
    asm("fma.rn.f32x2 %0, %1, %2, %0;" : "+l"(acc) : "l"(a), "l"(b));
}
__device__ __forceinline__ uint64_t add2(uint64_t a, uint64_t b) {
    uint64_t r;
    asm("add.rn.f32x2 %0, %1, %2;" : "=l"(r) : "l"(a), "l"(b));
    return r;
}
__device__ __forceinline__ void bar_sync(int id, int cnt) {
    asm volatile("bar.sync %0, %1;" :: "r"(id), "r"(cnt) : "memory");
}
__device__ __forceinline__ void bar_arrive(int id, int cnt) {
    asm volatile("bar.arrive %0, %1;" :: "r"(id), "r"(cnt) : "memory");
}

// One block per batch row, 256 threads.
//   warps 4-7 (tid 128..255): LSTM scan, warp = gate (i,f,g,o), lane = hidden dim.
//     (high warp-ids => arbiter priority on each SMSP)
//   warps 0-3 (tid 0..127):  epilogue consumers, h @ W_out per 32-step chunk.
// h history flows producer->consumer through an smem ring; no global hs buffer.
__global__ void __launch_bounds__(256, 1) fused_kernel(
    const float* __restrict__ x,      // (B, S)
    const float* __restrict__ bos,    // (D)
    const float* __restrict__ W_in,   // (1, D)
    const float* __restrict__ b_in,   // (D)
    const float* __restrict__ Wx,     // (D, 4D)
    const float* __restrict__ Wh,     // (D, 4D)
    const float* __restrict__ b_lstm, // (4D)
    const float* __restrict__ W_out,  // (D, C)
    const float* __restrict__ b_out,  // (C)
    float* __restrict__ out)          // (B, S, C)
{
    const int b   = blockIdx.x;
    const int tid = threadIdx.x;

    __shared__ float4 gbuf[2][32];       // [parity][dim] = {i,f,g,o} activated
    __shared__ float  hbuf[2][4][32];    // [parity][scan-warp][dim] private h copies
    __shared__ float  hring[RING][ND];   // h history ring (2 chunks)

    if (tid >= 128) {
        // ───────────────────────── scan warps ─────────────────────────
        const int st = tid - 128;
        const int w  = st >> 5;      // gate: 0=i 1=f 2=g 3=o
        const int l  = st & 31;      // hidden dim
        const int k  = st;           // gate column
        const bool sig = (w != 2);   // sigmoid gates get 0.5 pre-scale folded in

        // packed Wh column pairs (pre-scaled by 0.5 for sigmoid gates)
        const float ws = sig ? 0.5f : 1.0f;
        uint64_t whp[16];
#pragma unroll
        for (int j = 0; j < 16; j++)
            whp[j] = pack2(ws * Wh[(2 * j) * NG + k], ws * Wh[(2 * j + 1) * NG + k]);

        // rank-1 input path: z_in = x_prev*u + v ; step 0 uses bos embedding
        float u = 0.f, v = 0.f, z0 = 0.f;
#pragma unroll
        for (int d = 0; d < ND; d++) {
            float wx = Wx[d * NG + k];
            u  = fmaf(W_in[d], wx, u);
            v  = fmaf(b_in[d], wx, v);
            z0 = fmaf(bos[d],  wx, z0);
        }
        float bl = b_lstm[k];
        v = ws * (v + bl);
        z0 = ws * (z0 + bl);
        u *= ws;

        float c = 0.f;
        hbuf[1][w][l] = 0.f;         // parity-0 step reads hbuf[1]
        float zbase = z0;
        const float* xb = x + (size_t)b * NS;

#define STEP(P, S_) do {                                                     \
        float xn = __ldg(xb + (S_));                                         \
        __syncwarp();                                                        \
        const ulonglong2* hp = (const ulonglong2*)hbuf[(P) ^ 1][w];          \
        uint64_t a0 = pack2(zbase, 0.f), a1 = pack2(0.f, 0.f);               \
        _Pragma("unroll")                                                    \
        for (int j = 0; j < 8; j++) {                                        \
            ulonglong2 q = hp[j];                                            \
            fma2(a0, q.x, whp[2 * j + 0]);                                   \
            fma2(a1, q.y, whp[2 * j + 1]);                                   \
        }                                                                    \
        float zl, zh;                                                        \
        unpack2(zl, zh, add2(a0, a1));                                       \
        float z = zl + zh;                                                   \
        float t = tanh_fast(z);                                              \
        float act = sig ? fmaf(0.5f, t, 0.5f) : t;                           \
        ((float*)&gbuf[(P)][l])[w] = act;                                    \
        zbase = fmaf(xn, u, v);                                              \
        bar_sync(B_SCAN, 128);                                               \
        float4 g4 = gbuf[(P)][l];                                            \
        c = fmaf(g4.y, c, g4.x * g4.z);                                      \
        float h = g4.w * tanh_fast(c);                                       \
        hbuf[(P)][w][l] = h;                                                 \
        if (w == 0) hring[(S_) & (RING - 1)][l] = h;                         \
    } while (0)

        for (int n = 0; n < NCHUNK; n++) {
            if (n >= 2) bar_sync(B_FREE, 256);     // wait: chunk n-2 consumed
            int s0 = n * CHUNK;
#pragma unroll 2
            for (int s = s0; s < s0 + CHUNK; s += 2) {
                STEP(0, s);
                STEP(1, s + 1);
            }
            __threadfence_block();
            bar_arrive(B_READY, 256);              // publish chunk n
        }
#undef STEP
    } else {
        // ─────────────────────── consumer warps ───────────────────────
        // thread t -> output cols 2t, 2t+1 ; logits = h @ W_out + b_out
        const int t = tid;
        const int c0 = 2 * t, c1 = 2 * t + 1;

        uint64_t wv0[16], wv1[16];   // packed (W_out[2j][c], W_out[2j+1][c])
#pragma unroll
        for (int j = 0; j < 16; j++) {
            wv0[j] = pack2(W_out[(2 * j) * NC + c0], W_out[(2 * j + 1) * NC + c0]);
            wv1[j] = pack2(W_out[(2 * j) * NC + c1], W_out[(2 * j + 1) * NC + c1]);
        }
        const float bias0 = b_out[c0], bias1 = b_out[c1];
        float* ob = out + (size_t)b * NS * NC;

        for (int n = 0; n < NCHUNK; n++) {
            bar_sync(B_READY, 256);                // wait: chunk n published
            const float* base = &hring[(n & 1) * CHUNK][0];
            float* orow = ob + (size_t)n * CHUNK * NC;
#pragma unroll 2
            for (int r = 0; r < CHUNK; r++) {
                const ulonglong2* hr = (const ulonglong2*)(base + r * ND);
                uint64_t acc0 = pack2(bias0, 0.f);
                uint64_t acc1 = pack2(bias1, 0.f);
#pragma unroll
                for (int j = 0; j < 8; j++) {
                    ulonglong2 q = hr[j];
                    fma2(acc0, q.x, wv0[2 * j + 0]);
                    fma2(acc0, q.y, wv0[2 * j + 1]);
                    fma2(acc1, q.x, wv1[2 * j + 0]);
                    fma2(acc1, q.y, wv1[2 * j + 1]);
                }
                float e0, o0, e1, o1;
                unpack2(e0, o0, acc0);
                unpack2(e1, o1, acc1);
                float2 res = make_float2(e0 + o0, e1 + o1);
                ((float2*)(orow + r * NC))[t] = res;
            }
            bar_arrive(B_FREE, 256);               // release chunk n
        }
    }
}

extern "C" void kernel_launch(void* const* d_in, const int* in_sizes, int n_in,
                              void* d_out, int out_size)
{
    const float* x      = (const float*)d_in[0];
    const float* bos    = (const float*)d_in[1];
    const float* W_in   = (const float*)d_in[2];
    const float* b_in   = (const float*)d_in[3];
    const float* Wx     = (const float*)d_in[4];
    const float* Wh     = (const float*)d_in[5];
    const float* b_lstm = (const float*)d_in[6];
    const float* W_out  = (const float*)d_in[7];
    const float* b_out  = (const float*)d_in[8];

    fused_kernel<<<NB, 256>>>(x, bos, W_in, b_in, Wx, Wh, b_lstm,
                              W_out, b_out, (float*)d_out);
}